// round 2
// baseline (speedup 1.0000x reference)
#include <cuda_runtime.h>
#include <math.h>

// Problem constants
#define B_    16
#define NPTS  2048
#define PCTR  256
#define KNB   32
#define HW    1920          // 24*80
#define INFEA 64
#define MTOT  131072        // B_*PCTR*KNB
#define EPSBN 1e-5f
#define DIST_ 0.5f

// ---------------- scratch (static device globals; zero-initialized at load) ----------------
__device__ float g_X0[80 * MTOT];    // layer-1 input, channels 67..79 stay zero forever
__device__ float g_Y1[64 * MTOT];
__device__ float g_Y2[128 * MTOT];
__device__ float g_Y3[128 * MTOT];
__device__ float g_Y4[256 * MTOT];
__device__ int   g_idx[MTOT];
__device__ int   g_ridx[MTOT];
__device__ float g_vmask[B_ * PCTR];
__device__ float g_W1p[64 * 80];
__device__ float g_sum[4][256];
__device__ float g_sq[4][256];
__device__ float g_sc[4][256];
__device__ float g_sh[4][256];

// ---------------- kernel 1: depth-ball query (+ zero stats) ----------------
__global__ void k_idx(const float* __restrict__ pc,
                      const float* __restrict__ npc,
                      const int*   __restrict__ qv1)
{
    __shared__ float zs[NPTS];
    __shared__ int   stage[8][32];
    const int b   = blockIdx.x;
    const int tid = threadIdx.x;

    if (b == 0) {
        float* ps = &g_sum[0][0];
        float* pq = &g_sq[0][0];
        for (int i = tid; i < 4 * 256; i += 256) { ps[i] = 0.f; pq[i] = 0.f; }
    }
    for (int i = tid; i < NPTS; i += 256) zs[i] = pc[(b * 3 + 2) * NPTS + i];
    __syncthreads();

    const int w = tid >> 5, lane = tid & 31;
    for (int jj = 0; jj < 32; jj++) {
        const int j = w * 32 + jj;
        const float cz = npc[(b * 3 + 2) * PCTR + j];
        int cnt = 0;
        for (int c = 0; c < NPTS / 32; c++) {
            const int n = c * 32 + lane;
            const bool hit = fabsf(zs[n] - cz) < DIST_;
            const unsigned bal = __ballot_sync(0xffffffffu, hit);
            if (hit) {
                const int pos = cnt + __popc(bal & ((1u << lane) - 1u));
                if (pos < 32) stage[w][pos] = n;
            }
            cnt += __popc(bal);
            if (cnt >= 32) break;
        }
        __syncwarp();
        const int cc = min(cnt, 32);
        const int first = (cnt > 0) ? stage[w][0] : 0;
        const int v = (lane < cc) ? stage[w][lane] : first;
        const int gbase = (b * PCTR + j) * KNB;
        g_idx[gbase + lane]  = v;
        g_ridx[gbase + lane] = qv1[b * NPTS + v];
        if (lane == 0) g_vmask[b * PCTR + j] = (cnt > 0) ? 1.f : 0.f;
        __syncwarp();
    }
}

// ---------------- kernel: pad W1 (64x67 -> 64x80) ----------------
__global__ void k_padw1(const float* __restrict__ w1)
{
    for (int e = threadIdx.x; e < 64 * 80; e += 256) {
        const int r = e / 80, c = e % 80;
        g_W1p[e] = (c < 67) ? w1[r * 67 + c] : 0.f;
    }
}

// ---------------- kernel 2: gather X0 + write rgb channels into out ----------------
__global__ void k_gather(const float* __restrict__ pc,
                         const float* __restrict__ feat,
                         const float* __restrict__ img1,
                         const float* __restrict__ img2,
                         const float* __restrict__ npc,
                         float* __restrict__ out)
{
    __shared__ int   s_idx[32];
    __shared__ int   s_rid[32];
    __shared__ float s_np[3];
    __shared__ float s_vm;
    const int g = blockIdx.x;           // b*PCTR + j
    const int b = g >> 8;
    const int j = g & 255;
    const int t = threadIdx.x;
    const int mbase = g * KNB;

    if (t < 32) { s_idx[t] = g_idx[mbase + t]; s_rid[t] = g_ridx[mbase + t]; }
    if (t >= 32 && t < 35) s_np[t - 32] = npc[(b * 3 + (t - 32)) * PCTR + j];
    if (t == 40) s_vm = g_vmask[g];
    __syncthreads();

    const float vm = s_vm;
    const long ob = (long)b * (640 * 8192) + (long)j * 32;

    // pc channels (3 x 32)
    if (t < 96) {
        const int c = t >> 5, k = t & 31;
        g_X0[c * MTOT + mbase + k] = pc[(b * 3 + c) * NPTS + s_idx[k]] - s_np[c];
    }
    // feat channels (64 x 32)
    for (int e = t; e < INFEA * 32; e += 256) {
        const int c = e >> 5, k = e & 31;
        g_X0[(3 + c) * MTOT + mbase + k] = feat[(b * INFEA + c) * NPTS + s_idx[k]];
    }
    // rgb1 -> out channels [64,128)
    for (int e = t; e < 64 * 32; e += 256) {
        const int c = e >> 5, k = e & 31;
        out[ob + (long)(64 + c) * 8192 + k] = img1[(b * 64 + c) * HW + s_rid[k]] * vm;
    }
    // rgb2 -> out channels [256,384)
    for (int e = t; e < 128 * 32; e += 256) {
        const int c = e >> 5, k = e & 31;
        out[ob + (long)(256 + c) * 8192 + k] = img2[(b * 128 + c) * HW + s_rid[k]] * vm;
    }
}

// ---------------- fp32 GEMM: Y[BMgrid][M] = W @ normrelu(X), fused channel stats ----------------
template <int BM, int CIN, bool NORM_IN>
__global__ void k_gemm(const float* __restrict__ W,
                       const float* __restrict__ X,
                       float* __restrict__ Y,
                       const float* __restrict__ isc,
                       const float* __restrict__ ish,
                       float* __restrict__ osum,
                       float* __restrict__ osq)
{
    constexpr int BN = 128, BK = 8;
    constexpr int THREADS = (BM / 8) * 16;
    __shared__ float Ws[BK][BM];
    __shared__ float Xs[BK][BN];
    __shared__ float red[BM];

    const int tid = threadIdx.x;
    const int bn0 = blockIdx.x * BN;
    const int bm0 = blockIdx.y * BM;
    const int tn = tid & 15;
    const int tm = tid >> 4;

    float acc[8][8];
#pragma unroll
    for (int i = 0; i < 8; i++)
#pragma unroll
        for (int j = 0; j < 8; j++) acc[i][j] = 0.f;

    for (int k0 = 0; k0 < CIN; k0 += BK) {
        for (int e = tid; e < BM * BK; e += THREADS) {
            const int r = e >> 3, kk = e & 7;
            Ws[kk][r] = W[(bm0 + r) * CIN + k0 + kk];
        }
        for (int q = tid; q < BK * (BN / 4); q += THREADS) {
            const int kk = q >> 5, c4 = q & 31;
            float4 v = *(const float4*)&X[(k0 + kk) * MTOT + bn0 + c4 * 4];
            if (NORM_IN) {
                const float s = isc[k0 + kk], t = ish[k0 + kk];
                v.x = fmaxf(v.x * s + t, 0.f);
                v.y = fmaxf(v.y * s + t, 0.f);
                v.z = fmaxf(v.z * s + t, 0.f);
                v.w = fmaxf(v.w * s + t, 0.f);
            }
            *(float4*)&Xs[kk][c4 * 4] = v;
        }
        __syncthreads();
#pragma unroll
        for (int kk = 0; kk < BK; kk++) {
            float a[8], bb[8];
#pragma unroll
            for (int i = 0; i < 8; i++) a[i] = Ws[kk][tm * 8 + i];
#pragma unroll
            for (int j = 0; j < 8; j++) bb[j] = Xs[kk][tn * 8 + j];
#pragma unroll
            for (int i = 0; i < 8; i++)
#pragma unroll
                for (int j = 0; j < 8; j++) acc[i][j] = fmaf(a[i], bb[j], acc[i][j]);
        }
        __syncthreads();
    }

    // write Y (raw pre-BN)
#pragma unroll
    for (int i = 0; i < 8; i++) {
        const int row = bm0 + tm * 8 + i;
        float* yp = &Y[row * MTOT + bn0 + tn * 8];
        *(float4*)yp       = make_float4(acc[i][0], acc[i][1], acc[i][2], acc[i][3]);
        *(float4*)(yp + 4) = make_float4(acc[i][4], acc[i][5], acc[i][6], acc[i][7]);
    }

    // per-channel sum / sumsq
    for (int e = tid; e < BM; e += THREADS) red[e] = 0.f;
    __syncthreads();
#pragma unroll
    for (int i = 0; i < 8; i++) {
        float s = 0.f;
#pragma unroll
        for (int j = 0; j < 8; j++) s += acc[i][j];
        atomicAdd(&red[tm * 8 + i], s);
    }
    __syncthreads();
    for (int e = tid; e < BM; e += THREADS) atomicAdd(&osum[bm0 + e], red[e]);
    __syncthreads();
    for (int e = tid; e < BM; e += THREADS) red[e] = 0.f;
    __syncthreads();
#pragma unroll
    for (int i = 0; i < 8; i++) {
        float s = 0.f;
#pragma unroll
        for (int j = 0; j < 8; j++) s += acc[i][j] * acc[i][j];
        atomicAdd(&red[tm * 8 + i], s);
    }
    __syncthreads();
    for (int e = tid; e < BM; e += THREADS) atomicAdd(&osq[bm0 + e], red[e]);
}

// ---------------- stats -> (scale, shift) ----------------
__global__ void k_stats(int layer, const float* __restrict__ gam,
                        const float* __restrict__ bet, int C)
{
    const int c = threadIdx.x;
    if (c < C) {
        const float m = g_sum[layer][c] * (1.f / (float)MTOT);
        const float v = g_sq[layer][c] * (1.f / (float)MTOT) - m * m;
        const float s = gam[c] * rsqrtf(v + EPSBN);
        g_sc[layer][c] = s;
        g_sh[layer][c] = bet[c] - m * s;
    }
}

// ---------------- normalize + relu + valid-mask -> out channels [cbase, cbase+C) ----------------
__global__ void k_norm_out(const float* __restrict__ Y, int layer, int C, int cbase,
                           float* __restrict__ out)
{
    const int total4 = C * (MTOT / 4);
    for (int e = blockIdx.x * blockDim.x + threadIdx.x; e < total4;
         e += gridDim.x * blockDim.x) {
        const int c  = e / (MTOT / 4);
        const int m4 = e - c * (MTOT / 4);
        const int m  = m4 * 4;
        float4 y = *(const float4*)&Y[c * MTOT + m];
        const float s = g_sc[layer][c], t = g_sh[layer][c];
        const float vm = g_vmask[m >> 5];
        const int b = m >> 13;
        const int rem = m & 8191;
        float4 o;
        o.x = fmaxf(y.x * s + t, 0.f) * vm;
        o.y = fmaxf(y.y * s + t, 0.f) * vm;
        o.z = fmaxf(y.z * s + t, 0.f) * vm;
        o.w = fmaxf(y.w * s + t, 0.f) * vm;
        *(float4*)&out[(long)b * (640 * 8192) + (long)(cbase + c) * 8192 + rem] = o;
    }
}

// ---------------- launch ----------------
extern "C" void kernel_launch(void* const* d_in, const int* in_sizes, int n_in,
                              void* d_out, int out_size)
{
    const float* pc   = (const float*)d_in[0];
    const float* feat = (const float*)d_in[1];
    const float* img1 = (const float*)d_in[2];
    const float* img2 = (const float*)d_in[3];
    /* d_in[4] = P (unused by reference) */
    const int*   qv1  = (const int*)d_in[5];
    const float* npc  = (const float*)d_in[6];
    const float* w1 = (const float*)d_in[7];
    const float* g1 = (const float*)d_in[8];
    const float* b1 = (const float*)d_in[9];
    const float* w2 = (const float*)d_in[10];
    const float* g2 = (const float*)d_in[11];
    const float* b2 = (const float*)d_in[12];
    const float* w3 = (const float*)d_in[13];
    const float* g3 = (const float*)d_in[14];
    const float* b3 = (const float*)d_in[15];
    const float* w4 = (const float*)d_in[16];
    const float* g4 = (const float*)d_in[17];
    const float* b4 = (const float*)d_in[18];
    float* out = (float*)d_out;

    float *pX0, *pY1, *pY2, *pY3, *pY4, *pW1p, *pSum, *pSq, *pSc, *pSh;
    cudaGetSymbolAddress((void**)&pX0,  g_X0);
    cudaGetSymbolAddress((void**)&pY1,  g_Y1);
    cudaGetSymbolAddress((void**)&pY2,  g_Y2);
    cudaGetSymbolAddress((void**)&pY3,  g_Y3);
    cudaGetSymbolAddress((void**)&pY4,  g_Y4);
    cudaGetSymbolAddress((void**)&pW1p, g_W1p);
    cudaGetSymbolAddress((void**)&pSum, g_sum);
    cudaGetSymbolAddress((void**)&pSq,  g_sq);
    cudaGetSymbolAddress((void**)&pSc,  g_sc);
    cudaGetSymbolAddress((void**)&pSh,  g_sh);

    k_idx<<<B_, 256>>>(pc, npc, qv1);
    k_padw1<<<1, 256>>>(w1);
    k_gather<<<B_ * PCTR, 256>>>(pc, feat, img1, img2, npc, out);

    const int GX = MTOT / 128;

    // L1: 64 <- 80(pad of 67)
    k_gemm<64, 80, false><<<dim3(GX, 1), 128>>>(pW1p, pX0, pY1, nullptr, nullptr,
                                                pSum + 0 * 256, pSq + 0 * 256);
    k_stats<<<1, 256>>>(0, g1, b1, 64);
    k_norm_out<<<2048, 256>>>(pY1, 0, 64, 0, out);

    // L2: 128 <- 64
    k_gemm<128, 64, true><<<dim3(GX, 1), 256>>>(w2, pY1, pY2, pSc + 0 * 256, pSh + 0 * 256,
                                                pSum + 1 * 256, pSq + 1 * 256);
    k_stats<<<1, 256>>>(1, g2, b2, 128);
    k_norm_out<<<2048, 256>>>(pY2, 1, 128, 128, out);

    // L3: 128 <- 128
    k_gemm<128, 128, true><<<dim3(GX, 1), 256>>>(w3, pY2, pY3, pSc + 1 * 256, pSh + 1 * 256,
                                                 pSum + 2 * 256, pSq + 2 * 256);
    k_stats<<<1, 256>>>(2, g3, b3, 128);

    // L4: 256 <- 128
    k_gemm<128, 128, true><<<dim3(GX, 2), 256>>>(w4, pY3, pY4, pSc + 2 * 256, pSh + 2 * 256,
                                                 pSum + 3 * 256, pSq + 3 * 256);
    k_stats<<<1, 256>>>(3, g4, b4, 256);
    k_norm_out<<<2048, 256>>>(pY4, 3, 256, 384, out);
}

// round 3
// speedup vs baseline: 1.8035x; 1.8035x over previous
#include <cuda_runtime.h>
#include <math.h>

// Problem constants
#define B_    16
#define NPTS  2048
#define PCTR  256
#define KNB   32
#define HW    1920          // 24*80
#define INFEA 64
#define MTOT  131072        // B_*PCTR*KNB
#define EPSBN 1e-5f
#define DIST_ 0.5f

// ---------------- scratch (static device globals) ----------------
__device__ float g_X0[80 * MTOT];    // layer-1 input, channels 67..79 stay zero forever
__device__ float g_Y1[64 * MTOT];
__device__ float g_Y2[128 * MTOT];
__device__ float g_Y3[128 * MTOT];
__device__ float g_Y4[256 * MTOT];
__device__ int   g_idx[MTOT];
__device__ int   g_ridx[MTOT];
__device__ float g_vmask[B_ * PCTR];
__device__ float g_W1p[64 * 80];
__device__ float g_sum[4][256];
__device__ float g_sq[4][256];
__device__ float g_sc[4][256];
__device__ float g_sh[4][256];

__device__ __forceinline__ float t32(float x) {
    unsigned u;
    asm("cvt.rna.tf32.f32 %0, %1;" : "=r"(u) : "f"(x));
    return __uint_as_float(u);
}

// ---------------- kernel 1: depth-ball query (+ zero stats) ----------------
__global__ void k_idx(const float* __restrict__ pc,
                      const float* __restrict__ npc,
                      const int*   __restrict__ qv1)
{
    __shared__ float zs[NPTS];
    __shared__ int   stage[8][32];
    const int b   = blockIdx.x;
    const int tid = threadIdx.x;

    if (b == 0) {
        float* ps = &g_sum[0][0];
        float* pq = &g_sq[0][0];
        for (int i = tid; i < 4 * 256; i += 256) { ps[i] = 0.f; pq[i] = 0.f; }
    }
    for (int i = tid; i < NPTS; i += 256) zs[i] = pc[(b * 3 + 2) * NPTS + i];
    __syncthreads();

    const int w = tid >> 5, lane = tid & 31;
    for (int jj = 0; jj < 32; jj++) {
        const int j = w * 32 + jj;
        const float cz = npc[(b * 3 + 2) * PCTR + j];
        int cnt = 0;
        for (int c = 0; c < NPTS / 32; c++) {
            const int n = c * 32 + lane;
            const bool hit = fabsf(zs[n] - cz) < DIST_;
            const unsigned bal = __ballot_sync(0xffffffffu, hit);
            if (hit) {
                const int pos = cnt + __popc(bal & ((1u << lane) - 1u));
                if (pos < 32) stage[w][pos] = n;
            }
            cnt += __popc(bal);
            if (cnt >= 32) break;
        }
        __syncwarp();
        const int cc = min(cnt, 32);
        const int first = (cnt > 0) ? stage[w][0] : 0;
        const int v = (lane < cc) ? stage[w][lane] : first;
        const int gbase = (b * PCTR + j) * KNB;
        g_idx[gbase + lane]  = v;
        g_ridx[gbase + lane] = qv1[b * NPTS + v];
        if (lane == 0) g_vmask[b * PCTR + j] = (cnt > 0) ? 1.f : 0.f;
        __syncwarp();
    }
}

// ---------------- kernel: pad W1 (64x67 -> 64x80) ----------------
__global__ void k_padw1(const float* __restrict__ w1)
{
    for (int e = threadIdx.x; e < 64 * 80; e += 256) {
        const int r = e / 80, c = e % 80;
        g_W1p[e] = (c < 67) ? w1[r * 67 + c] : 0.f;
    }
}

// ---------------- kernel 2: gather X0 + write rgb channels into out ----------------
__global__ void k_gather(const float* __restrict__ pc,
                         const float* __restrict__ feat,
                         const float* __restrict__ img1,
                         const float* __restrict__ img2,
                         const float* __restrict__ npc,
                         float* __restrict__ out)
{
    __shared__ int   s_idx[32];
    __shared__ int   s_rid[32];
    __shared__ float s_np[3];
    __shared__ float s_vm;
    const int g = blockIdx.x;           // b*PCTR + j
    const int b = g >> 8;
    const int j = g & 255;
    const int t = threadIdx.x;
    const int mbase = g * KNB;

    if (t < 32) { s_idx[t] = g_idx[mbase + t]; s_rid[t] = g_ridx[mbase + t]; }
    if (t >= 32 && t < 35) s_np[t - 32] = npc[(b * 3 + (t - 32)) * PCTR + j];
    if (t == 40) s_vm = g_vmask[g];
    __syncthreads();

    const float vm = s_vm;
    const long ob = (long)b * (640 * 8192) + (long)j * 32;

    if (t < 96) {
        const int c = t >> 5, k = t & 31;
        g_X0[c * MTOT + mbase + k] = pc[(b * 3 + c) * NPTS + s_idx[k]] - s_np[c];
    }
    for (int e = t; e < INFEA * 32; e += 256) {
        const int c = e >> 5, k = e & 31;
        g_X0[(3 + c) * MTOT + mbase + k] = feat[(b * INFEA + c) * NPTS + s_idx[k]];
    }
    for (int e = t; e < 64 * 32; e += 256) {
        const int c = e >> 5, k = e & 31;
        out[ob + (long)(64 + c) * 8192 + k] = img1[(b * 64 + c) * HW + s_rid[k]] * vm;
    }
    for (int e = t; e < 128 * 32; e += 256) {
        const int c = e >> 5, k = e & 31;
        out[ob + (long)(256 + c) * 8192 + k] = img2[(b * 128 + c) * HW + s_rid[k]] * vm;
    }
}

// ---------------- tf32 tensor-core GEMM: Y = W @ normrelu(X), fused stats ----------------
// Block tile: BM x 128, warp tile 64x32, mma m16n8k8 tf32.
template <int BM, int CIN, bool NORM_IN>
__global__ void k_gemm_tc(const float* __restrict__ W,
                          const float* __restrict__ X,
                          float* __restrict__ Y,
                          const float* __restrict__ isc,
                          const float* __restrict__ ish,
                          float* __restrict__ osum,
                          float* __restrict__ osq)
{
    constexpr int BN = 128, BK = 16;
    constexpr int WARPS_M = BM / 64;
    constexpr int WARPS_N = 4;                  // BN / 32
    constexpr int THREADS = WARPS_M * WARPS_N * 32;
    __shared__ float As[BK][BM + 4];
    __shared__ float Bs[BK][BN + 4];
    __shared__ float redS[BM];
    __shared__ float redQ[BM];

    const int tid  = threadIdx.x;
    const int lane = tid & 31;
    const int warp = tid >> 5;
    const int wm0  = (warp / WARPS_N) * 64;
    const int wn0  = (warp % WARPS_N) * 32;
    const int bn0  = blockIdx.x * BN;
    const int bm0  = blockIdx.y * BM;
    const int grp  = lane >> 2;   // 0..7
    const int tig  = lane & 3;    // 0..3

    float acc[4][4][4];
#pragma unroll
    for (int mi = 0; mi < 4; mi++)
#pragma unroll
        for (int ni = 0; ni < 4; ni++)
#pragma unroll
            for (int r = 0; r < 4; r++) acc[mi][ni][r] = 0.f;

    for (int k0 = 0; k0 < CIN; k0 += BK) {
        // A: W[bm0+r][k0..k0+16) -> As[k][r], tf32-rounded
        for (int e = tid; e < BM * (BK / 4); e += THREADS) {
            const int r  = e >> 2;
            const int kq = (e & 3) * 4;
            float4 v = *(const float4*)&W[(bm0 + r) * CIN + k0 + kq];
            As[kq + 0][r] = t32(v.x);
            As[kq + 1][r] = t32(v.y);
            As[kq + 2][r] = t32(v.z);
            As[kq + 3][r] = t32(v.w);
        }
        // B: X[k0+kk][bn0..bn0+128) -> Bs[kk][:], norm-relu + tf32-round
        for (int e = tid; e < BK * (BN / 4); e += THREADS) {
            const int kk = e >> 5;
            const int c4 = (e & 31) * 4;
            float4 v = *(const float4*)&X[(k0 + kk) * MTOT + bn0 + c4];
            if (NORM_IN) {
                const float s = isc[k0 + kk], t = ish[k0 + kk];
                v.x = fmaxf(v.x * s + t, 0.f);
                v.y = fmaxf(v.y * s + t, 0.f);
                v.z = fmaxf(v.z * s + t, 0.f);
                v.w = fmaxf(v.w * s + t, 0.f);
            }
            v.x = t32(v.x); v.y = t32(v.y); v.z = t32(v.z); v.w = t32(v.w);
            *(float4*)&Bs[kk][c4] = v;
        }
        __syncthreads();

#pragma unroll
        for (int kk = 0; kk < 2; kk++) {
            const int kb = kk * 8;
            unsigned a[4][4], b[4][2];
#pragma unroll
            for (int mi = 0; mi < 4; mi++) {
                const int r1 = wm0 + mi * 16 + grp;
                a[mi][0] = __float_as_uint(As[kb + tig][r1]);
                a[mi][1] = __float_as_uint(As[kb + tig][r1 + 8]);
                a[mi][2] = __float_as_uint(As[kb + tig + 4][r1]);
                a[mi][3] = __float_as_uint(As[kb + tig + 4][r1 + 8]);
            }
#pragma unroll
            for (int ni = 0; ni < 4; ni++) {
                const int c = wn0 + ni * 8 + grp;
                b[ni][0] = __float_as_uint(Bs[kb + tig][c]);
                b[ni][1] = __float_as_uint(Bs[kb + tig + 4][c]);
            }
#pragma unroll
            for (int mi = 0; mi < 4; mi++)
#pragma unroll
                for (int ni = 0; ni < 4; ni++) {
                    asm volatile(
                        "mma.sync.aligned.m16n8k8.row.col.f32.tf32.tf32.f32 "
                        "{%0,%1,%2,%3}, {%4,%5,%6,%7}, {%8,%9}, {%0,%1,%2,%3};"
                        : "+f"(acc[mi][ni][0]), "+f"(acc[mi][ni][1]),
                          "+f"(acc[mi][ni][2]), "+f"(acc[mi][ni][3])
                        : "r"(a[mi][0]), "r"(a[mi][1]), "r"(a[mi][2]), "r"(a[mi][3]),
                          "r"(b[ni][0]), "r"(b[ni][1]));
                }
        }
        __syncthreads();
    }

    // stats init
    for (int e = tid; e < BM; e += THREADS) { redS[e] = 0.f; redQ[e] = 0.f; }
    __syncthreads();

    // write Y + accumulate per-channel stats
#pragma unroll
    for (int mi = 0; mi < 4; mi++) {
        const int r1 = wm0 + mi * 16 + grp;
        const int r2 = r1 + 8;
        float s1 = 0.f, q1 = 0.f, s2 = 0.f, q2 = 0.f;
#pragma unroll
        for (int ni = 0; ni < 4; ni++) {
            const int c = bn0 + wn0 + ni * 8 + tig * 2;
            *(float2*)&Y[(long)(bm0 + r1) * MTOT + c] =
                make_float2(acc[mi][ni][0], acc[mi][ni][1]);
            *(float2*)&Y[(long)(bm0 + r2) * MTOT + c] =
                make_float2(acc[mi][ni][2], acc[mi][ni][3]);
            s1 += acc[mi][ni][0] + acc[mi][ni][1];
            q1 += acc[mi][ni][0] * acc[mi][ni][0] + acc[mi][ni][1] * acc[mi][ni][1];
            s2 += acc[mi][ni][2] + acc[mi][ni][3];
            q2 += acc[mi][ni][2] * acc[mi][ni][2] + acc[mi][ni][3] * acc[mi][ni][3];
        }
        atomicAdd(&redS[r1], s1);
        atomicAdd(&redQ[r1], q1);
        atomicAdd(&redS[r2], s2);
        atomicAdd(&redQ[r2], q2);
    }
    __syncthreads();
    for (int e = tid; e < BM; e += THREADS) {
        atomicAdd(&osum[bm0 + e], redS[e]);
        atomicAdd(&osq[bm0 + e], redQ[e]);
    }
}

// ---------------- stats -> (scale, shift) ----------------
__global__ void k_stats(int layer, const float* __restrict__ gam,
                        const float* __restrict__ bet, int C)
{
    const int c = threadIdx.x;
    if (c < C) {
        const float m = g_sum[layer][c] * (1.f / (float)MTOT);
        const float v = g_sq[layer][c] * (1.f / (float)MTOT) - m * m;
        const float s = gam[c] * rsqrtf(v + EPSBN);
        g_sc[layer][c] = s;
        g_sh[layer][c] = bet[c] - m * s;
    }
}

// ---------------- normalize + relu + valid-mask -> out ----------------
__global__ void k_norm_out(const float* __restrict__ Y, int layer, int C, int cbase,
                           float* __restrict__ out)
{
    const int total4 = C * (MTOT / 4);
    for (int e = blockIdx.x * blockDim.x + threadIdx.x; e < total4;
         e += gridDim.x * blockDim.x) {
        const int c  = e / (MTOT / 4);
        const int m4 = e - c * (MTOT / 4);
        const int m  = m4 * 4;
        float4 y = *(const float4*)&Y[(long)c * MTOT + m];
        const float s = g_sc[layer][c], t = g_sh[layer][c];
        const float vm = g_vmask[m >> 5];
        const int b = m >> 13;
        const int rem = m & 8191;
        float4 o;
        o.x = fmaxf(y.x * s + t, 0.f) * vm;
        o.y = fmaxf(y.y * s + t, 0.f) * vm;
        o.z = fmaxf(y.z * s + t, 0.f) * vm;
        o.w = fmaxf(y.w * s + t, 0.f) * vm;
        *(float4*)&out[(long)b * (640 * 8192) + (long)(cbase + c) * 8192 + rem] = o;
    }
}

// ---------------- launch ----------------
extern "C" void kernel_launch(void* const* d_in, const int* in_sizes, int n_in,
                              void* d_out, int out_size)
{
    const float* pc   = (const float*)d_in[0];
    const float* feat = (const float*)d_in[1];
    const float* img1 = (const float*)d_in[2];
    const float* img2 = (const float*)d_in[3];
    const int*   qv1  = (const int*)d_in[5];
    const float* npc  = (const float*)d_in[6];
    const float* w1 = (const float*)d_in[7];
    const float* g1 = (const float*)d_in[8];
    const float* b1 = (const float*)d_in[9];
    const float* w2 = (const float*)d_in[10];
    const float* g2 = (const float*)d_in[11];
    const float* b2 = (const float*)d_in[12];
    const float* w3 = (const float*)d_in[13];
    const float* g3 = (const float*)d_in[14];
    const float* b3 = (const float*)d_in[15];
    const float* w4 = (const float*)d_in[16];
    const float* g4 = (const float*)d_in[17];
    const float* b4 = (const float*)d_in[18];
    float* out = (float*)d_out;

    float *pX0, *pY1, *pY2, *pY3, *pY4, *pW1p, *pSum, *pSq, *pSc, *pSh;
    cudaGetSymbolAddress((void**)&pX0,  g_X0);
    cudaGetSymbolAddress((void**)&pY1,  g_Y1);
    cudaGetSymbolAddress((void**)&pY2,  g_Y2);
    cudaGetSymbolAddress((void**)&pY3,  g_Y3);
    cudaGetSymbolAddress((void**)&pY4,  g_Y4);
    cudaGetSymbolAddress((void**)&pW1p, g_W1p);
    cudaGetSymbolAddress((void**)&pSum, g_sum);
    cudaGetSymbolAddress((void**)&pSq,  g_sq);
    cudaGetSymbolAddress((void**)&pSc,  g_sc);
    cudaGetSymbolAddress((void**)&pSh,  g_sh);

    k_idx<<<B_, 256>>>(pc, npc, qv1);
    k_padw1<<<1, 256>>>(w1);
    k_gather<<<B_ * PCTR, 256>>>(pc, feat, img1, img2, npc, out);

    const int GX = MTOT / 128;

    // L1: 64 <- 80(pad of 67)
    k_gemm_tc<64, 80, false><<<dim3(GX, 1), 128>>>(pW1p, pX0, pY1, nullptr, nullptr,
                                                   pSum + 0 * 256, pSq + 0 * 256);
    k_stats<<<1, 256>>>(0, g1, b1, 64);
    k_norm_out<<<2048, 256>>>(pY1, 0, 64, 0, out);

    // L2: 128 <- 64
    k_gemm_tc<128, 64, true><<<dim3(GX, 1), 256>>>(w2, pY1, pY2, pSc + 0 * 256, pSh + 0 * 256,
                                                   pSum + 1 * 256, pSq + 1 * 256);
    k_stats<<<1, 256>>>(1, g2, b2, 128);
    k_norm_out<<<2048, 256>>>(pY2, 1, 128, 128, out);

    // L3: 128 <- 128
    k_gemm_tc<128, 128, true><<<dim3(GX, 1), 256>>>(w3, pY2, pY3, pSc + 1 * 256, pSh + 1 * 256,
                                                    pSum + 2 * 256, pSq + 2 * 256);
    k_stats<<<1, 256>>>(2, g3, b3, 128);

    // L4: 256 <- 128
    k_gemm_tc<128, 128, true><<<dim3(GX, 2), 256>>>(w4, pY3, pY4, pSc + 2 * 256, pSh + 2 * 256,
                                                    pSum + 3 * 256, pSq + 3 * 256);
    k_stats<<<1, 256>>>(3, g4, b4, 256);
    k_norm_out<<<2048, 256>>>(pY4, 3, 256, 384, out);
}

// round 4
// speedup vs baseline: 2.8694x; 1.5911x over previous
#include <cuda_runtime.h>
#include <cuda_fp16.h>
#include <math.h>

#define B_    16
#define NPTS  2048
#define PCTR  256
#define KNB   32
#define HW    1920
#define INFEA 64
#define MTOT  131072
#define EPSBN 1e-5f
#define DIST_ 0.5f
#define OUTSTRIDE 5242880   // 640*8192

// ---------------- scratch ----------------
__device__ __half g_X0h[96 * MTOT];   // channels 67..95 stay zero
__device__ __half g_Y1h[64 * MTOT];
__device__ __half g_Y2h[128 * MTOT];
__device__ __half g_Y3h[128 * MTOT];
__device__ __half g_Y4h[256 * MTOT];
__device__ int    g_idx[MTOT];
__device__ int    g_ridx[MTOT];
__device__ float  g_vmask[B_ * PCTR];
__device__ unsigned g_Wp1[48 * 64];    // half2 packed [CINP/2][M]
__device__ unsigned g_Wp2[32 * 128];
__device__ unsigned g_Wp3[64 * 128];
__device__ unsigned g_Wp4[64 * 256];
__device__ float  g_sum[4][256];
__device__ float  g_sq[4][256];
__device__ float  g_sc[4][256];
__device__ float  g_sh[4][256];

// ---------------- depth-ball query ----------------
__global__ void k_idx(const float* __restrict__ pc,
                      const float* __restrict__ npc,
                      const int*   __restrict__ qv1)
{
    __shared__ float zs[NPTS];
    __shared__ int   stage[8][32];
    const int b   = blockIdx.x;
    const int tid = threadIdx.x;

    if (b == 0) {
        float* ps = &g_sum[0][0];
        float* pq = &g_sq[0][0];
        for (int i = tid; i < 4 * 256; i += 256) { ps[i] = 0.f; pq[i] = 0.f; }
    }
    for (int i = tid; i < NPTS; i += 256) zs[i] = pc[(b * 3 + 2) * NPTS + i];
    __syncthreads();

    const int w = tid >> 5, lane = tid & 31;
    for (int jj = 0; jj < 32; jj++) {
        const int j = w * 32 + jj;
        const float cz = npc[(b * 3 + 2) * PCTR + j];
        int cnt = 0;
        for (int c = 0; c < NPTS / 32; c++) {
            const int n = c * 32 + lane;
            const bool hit = fabsf(zs[n] - cz) < DIST_;
            const unsigned bal = __ballot_sync(0xffffffffu, hit);
            if (hit) {
                const int pos = cnt + __popc(bal & ((1u << lane) - 1u));
                if (pos < 32) stage[w][pos] = n;
            }
            cnt += __popc(bal);
            if (cnt >= 32) break;
        }
        __syncwarp();
        const int cc = min(cnt, 32);
        const int first = (cnt > 0) ? stage[w][0] : 0;
        const int v = (lane < cc) ? stage[w][lane] : first;
        const int gbase = (b * PCTR + j) * KNB;
        g_idx[gbase + lane]  = v;
        g_ridx[gbase + lane] = qv1[b * NPTS + v];
        if (lane == 0) g_vmask[b * PCTR + j] = (cnt > 0) ? 1.f : 0.f;
        __syncwarp();
    }
}

// ---------------- weight packing: Wp[p][m] = half2{w[m][2p], w[m][2p+1]} ----------------
__device__ __forceinline__ void packW(const float* w, unsigned* dst,
                                      int M, int CIN, int CINP, int tid, int nthr)
{
    const int tot = (CINP / 2) * M;
    for (int i = tid; i < tot; i += nthr) {
        const int p = i / M, m = i - p * M;
        const int k0 = 2 * p, k1 = 2 * p + 1;
        const float a = (k0 < CIN) ? w[m * CIN + k0] : 0.f;
        const float b = (k1 < CIN) ? w[m * CIN + k1] : 0.f;
        __half2 h = __floats2half2_rn(a, b);
        dst[i] = *(unsigned*)&h;
    }
}

__global__ void k_prep(const float* __restrict__ w1, const float* __restrict__ w2,
                       const float* __restrict__ w3, const float* __restrict__ w4)
{
    const int tid = blockIdx.x * blockDim.x + threadIdx.x;
    const int nthr = gridDim.x * blockDim.x;
    packW(w1, g_Wp1, 64, 67, 96, tid, nthr);
    packW(w2, g_Wp2, 128, 64, 64, tid, nthr);
    packW(w3, g_Wp3, 128, 128, 128, tid, nthr);
    packW(w4, g_Wp4, 256, 128, 128, tid, nthr);
}

// ---------------- gather X0 (half) + rgb -> out ----------------
__global__ void k_gather(const float* __restrict__ pc,
                         const float* __restrict__ feat,
                         const float* __restrict__ img1,
                         const float* __restrict__ img2,
                         const float* __restrict__ npc,
                         float* __restrict__ out)
{
    __shared__ int   s_idx[32];
    __shared__ int   s_rid[32];
    __shared__ float s_np[3];
    __shared__ float s_vm;
    const int g = blockIdx.x;
    const int b = g >> 8;
    const int j = g & 255;
    const int t = threadIdx.x;
    const int mbase = g * KNB;

    if (t < 32) { s_idx[t] = g_idx[mbase + t]; s_rid[t] = g_ridx[mbase + t]; }
    if (t >= 32 && t < 35) s_np[t - 32] = npc[(b * 3 + (t - 32)) * PCTR + j];
    if (t == 40) s_vm = g_vmask[g];
    __syncthreads();

    const float vm = s_vm;
    const long ob = (long)b * OUTSTRIDE + (long)j * 32;

    if (t < 96) {
        const int c = t >> 5, k = t & 31;
        g_X0h[c * MTOT + mbase + k] =
            __float2half(pc[(b * 3 + c) * NPTS + s_idx[k]] - s_np[c]);
    }
    for (int e = t; e < INFEA * 32; e += 256) {
        const int c = e >> 5, k = e & 31;
        g_X0h[(3 + c) * MTOT + mbase + k] =
            __float2half(feat[(b * INFEA + c) * NPTS + s_idx[k]]);
    }
    for (int e = t; e < 64 * 32; e += 256) {
        const int c = e >> 5, k = e & 31;
        out[ob + (long)(64 + c) * 8192 + k] = img1[(b * 64 + c) * HW + s_rid[k]] * vm;
    }
    for (int e = t; e < 128 * 32; e += 256) {
        const int c = e >> 5, k = e & 31;
        out[ob + (long)(256 + c) * 8192 + k] = img2[(b * 128 + c) * HW + s_rid[k]] * vm;
    }
}

// ---------------- fp16 tensor-core GEMM, register-prefetch pipeline ----------------
// Y[BM][MTOT](half) = W(BMxCIN) @ f(X)   where f = optional norm+relu
// Fused: per-channel sum/sumsq stats; optional fp32 normalized X write to out.
template <int BM, int CIN, bool NORM_IN, int OUTC, int THREADS>
__global__ void __launch_bounds__(THREADS)
k_gemm_h(const unsigned* __restrict__ Wp, const __half* __restrict__ X,
         __half* __restrict__ Y,
         const float* __restrict__ isc, const float* __restrict__ ish,
         float* __restrict__ osum, float* __restrict__ osq,
         float* __restrict__ out)
{
    constexpr int BN = 128, BK = 32, KP = 16;
    constexpr int NITER = CIN / BK;
    constexpr int WARPS_M = THREADS / 128;      // WARPS_N = 4
    constexpr int WTM = BM / WARPS_M;
    constexpr int MI = WTM / 16;
    constexpr int AIT = KP * (BM / 4);          // uint4 items per stage
    constexpr int AITER = AIT / THREADS;
    constexpr int BITER = 512 / THREADS;        // B items: 16 kpairs x 32 n4

    __shared__ __half2 As2[KP][BM + 8];
    __shared__ __half2 Bs2[KP][BN + 8];
    __shared__ float redS[BM], redQ[BM];

    const int tid  = threadIdx.x;
    const int lane = tid & 31;
    const int warp = tid >> 5;
    const int wm0  = (warp >> 2) * WTM;
    const int wn0  = (warp & 3) * 32;
    const int bn0  = blockIdx.x * BN;
    const int grp  = lane >> 2;
    const int tig  = lane & 3;

    uint4 aReg[AITER];
    uint4 bReg[BITER];

    // ---- loaders ----
    auto loadA = [&](int k0) {
#pragma unroll
        for (int u = 0; u < AITER; u++) {
            const int f = tid + u * THREADS;
            const int kk2 = f / (BM / 4), m4 = f % (BM / 4);
            aReg[u] = *(const uint4*)&Wp[(k0 / 2 + kk2) * BM + m4 * 4];
        }
    };
    auto storeA = [&]() {
#pragma unroll
        for (int u = 0; u < AITER; u++) {
            const int f = tid + u * THREADS;
            const int kk2 = f / (BM / 4), m4 = f % (BM / 4);
            *(uint4*)&As2[kk2][m4 * 4] = aReg[u];
        }
    };
    auto loadB = [&](int k0) {
#pragma unroll
        for (int u = 0; u < BITER; u++) {
            const int e = tid + u * THREADS;
            const int kk2 = e >> 5;
            const int n = bn0 + (e & 31) * 4;
            const int k = k0 + 2 * kk2;
            const uint2 r0 = *(const uint2*)&X[(size_t)k * MTOT + n];
            const uint2 r1 = *(const uint2*)&X[(size_t)(k + 1) * MTOT + n];
            const __half* h0 = (const __half*)&r0;
            const __half* h1 = (const __half*)&r1;
            float v0[4], v1[4];
#pragma unroll
            for (int j = 0; j < 4; j++) { v0[j] = __half2float(h0[j]); v1[j] = __half2float(h1[j]); }
            if (NORM_IN) {
                const float s0 = isc[k], t0 = ish[k];
                const float s1 = isc[k + 1], t1 = ish[k + 1];
#pragma unroll
                for (int j = 0; j < 4; j++) {
                    v0[j] = fmaxf(v0[j] * s0 + t0, 0.f);
                    v1[j] = fmaxf(v1[j] * s1 + t1, 0.f);
                }
            }
            if (OUTC >= 0) {
                const float vm = g_vmask[n >> 5];
                const int bb = n >> 13, rem = n & 8191;
                float* op = &out[(long)bb * OUTSTRIDE + (long)(OUTC + k) * 8192 + rem];
                *(float4*)op = make_float4(v0[0] * vm, v0[1] * vm, v0[2] * vm, v0[3] * vm);
                op += 8192;
                *(float4*)op = make_float4(v1[0] * vm, v1[1] * vm, v1[2] * vm, v1[3] * vm);
            }
            __half2 h[4];
#pragma unroll
            for (int j = 0; j < 4; j++) h[j] = __floats2half2_rn(v0[j], v1[j]);
            bReg[u] = *(uint4*)h;
        }
    };
    auto storeB = [&]() {
#pragma unroll
        for (int u = 0; u < BITER; u++) {
            const int e = tid + u * THREADS;
            const int kk2 = e >> 5;
            const int n4 = e & 31;
            *(uint4*)&Bs2[kk2][n4 * 4] = bReg[u];
        }
    };

    float acc[MI][4][4];
#pragma unroll
    for (int mi = 0; mi < MI; mi++)
#pragma unroll
        for (int ni = 0; ni < 4; ni++)
#pragma unroll
            for (int r = 0; r < 4; r++) acc[mi][ni][r] = 0.f;

    // ---- pipeline ----
    loadA(0); loadB(0);
    storeA(); storeB();
    __syncthreads();

    for (int it = 0; it < NITER; it++) {
        if (it + 1 < NITER) { loadA((it + 1) * BK); loadB((it + 1) * BK); }
#pragma unroll
        for (int ks = 0; ks < 2; ks++) {
            const int kb = ks * 8;
            unsigned a[MI][4], b[4][2];
#pragma unroll
            for (int mi = 0; mi < MI; mi++) {
                const int row = wm0 + mi * 16 + grp;
                a[mi][0] = *(const unsigned*)&As2[kb + tig][row];
                a[mi][1] = *(const unsigned*)&As2[kb + tig][row + 8];
                a[mi][2] = *(const unsigned*)&As2[kb + tig + 4][row];
                a[mi][3] = *(const unsigned*)&As2[kb + tig + 4][row + 8];
            }
#pragma unroll
            for (int ni = 0; ni < 4; ni++) {
                const int col = wn0 + ni * 8 + grp;
                b[ni][0] = *(const unsigned*)&Bs2[kb + tig][col];
                b[ni][1] = *(const unsigned*)&Bs2[kb + tig + 4][col];
            }
#pragma unroll
            for (int mi = 0; mi < MI; mi++)
#pragma unroll
                for (int ni = 0; ni < 4; ni++) {
                    asm volatile(
                        "mma.sync.aligned.m16n8k16.row.col.f32.f16.f16.f32 "
                        "{%0,%1,%2,%3}, {%4,%5,%6,%7}, {%8,%9}, {%0,%1,%2,%3};"
                        : "+f"(acc[mi][ni][0]), "+f"(acc[mi][ni][1]),
                          "+f"(acc[mi][ni][2]), "+f"(acc[mi][ni][3])
                        : "r"(a[mi][0]), "r"(a[mi][1]), "r"(a[mi][2]), "r"(a[mi][3]),
                          "r"(b[ni][0]), "r"(b[ni][1]));
                }
        }
        __syncthreads();
        if (it + 1 < NITER) { storeA(); storeB(); __syncthreads(); }
    }

    // ---- epilogue: Y(half) + stats ----
    for (int e = tid; e < BM; e += THREADS) { redS[e] = 0.f; redQ[e] = 0.f; }
    __syncthreads();

#pragma unroll
    for (int mi = 0; mi < MI; mi++) {
        const int r1 = wm0 + mi * 16 + grp;
        const int r2 = r1 + 8;
        float s1 = 0.f, q1 = 0.f, s2 = 0.f, q2 = 0.f;
#pragma unroll
        for (int ni = 0; ni < 4; ni++) {
            const int col = bn0 + wn0 + ni * 8 + tig * 2;
            const float c0 = acc[mi][ni][0], c1 = acc[mi][ni][1];
            const float c2 = acc[mi][ni][2], c3 = acc[mi][ni][3];
            *(__half2*)&Y[(size_t)r1 * MTOT + col] = __floats2half2_rn(c0, c1);
            *(__half2*)&Y[(size_t)r2 * MTOT + col] = __floats2half2_rn(c2, c3);
            s1 += c0 + c1;  q1 += c0 * c0 + c1 * c1;
            s2 += c2 + c3;  q2 += c2 * c2 + c3 * c3;
        }
        atomicAdd(&redS[r1], s1);
        atomicAdd(&redQ[r1], q1);
        atomicAdd(&redS[r2], s2);
        atomicAdd(&redQ[r2], q2);
    }
    __syncthreads();
    for (int e = tid; e < BM; e += THREADS) {
        atomicAdd(&osum[e], redS[e]);
        atomicAdd(&osq[e], redQ[e]);
    }
}

// ---------------- stats -> (scale, shift) ----------------
__global__ void k_stats(int layer, const float* __restrict__ gam,
                        const float* __restrict__ bet, int C)
{
    const int c = threadIdx.x;
    if (c < C) {
        const float m = g_sum[layer][c] * (1.f / (float)MTOT);
        const float v = g_sq[layer][c] * (1.f / (float)MTOT) - m * m;
        const float s = gam[c] * rsqrtf(v + EPSBN);
        g_sc[layer][c] = s;
        g_sh[layer][c] = bet[c] - m * s;
    }
}

// ---------------- final norm_out for Y4 (half in, fp32 out) ----------------
__global__ void k_norm_out_h(const __half* __restrict__ Y, int layer, int C, int cbase,
                             float* __restrict__ out)
{
    const int T = C * (MTOT / 8);
    for (int e = blockIdx.x * blockDim.x + threadIdx.x; e < T;
         e += gridDim.x * blockDim.x) {
        const int c  = e / (MTOT / 8);
        const int m  = (e - c * (MTOT / 8)) * 8;
        const uint4 r = *(const uint4*)&Y[(size_t)c * MTOT + m];
        const __half* h = (const __half*)&r;
        const float s = g_sc[layer][c], t = g_sh[layer][c];
        const float vm = g_vmask[m >> 5];
        const int bb = m >> 13, rem = m & 8191;
        float* op = &out[(long)bb * OUTSTRIDE + (long)(cbase + c) * 8192 + rem];
        float4 o0, o1;
        o0.x = fmaxf(__half2float(h[0]) * s + t, 0.f) * vm;
        o0.y = fmaxf(__half2float(h[1]) * s + t, 0.f) * vm;
        o0.z = fmaxf(__half2float(h[2]) * s + t, 0.f) * vm;
        o0.w = fmaxf(__half2float(h[3]) * s + t, 0.f) * vm;
        o1.x = fmaxf(__half2float(h[4]) * s + t, 0.f) * vm;
        o1.y = fmaxf(__half2float(h[5]) * s + t, 0.f) * vm;
        o1.z = fmaxf(__half2float(h[6]) * s + t, 0.f) * vm;
        o1.w = fmaxf(__half2float(h[7]) * s + t, 0.f) * vm;
        *(float4*)op       = o0;
        *(float4*)(op + 4) = o1;
    }
}

// ---------------- launch ----------------
extern "C" void kernel_launch(void* const* d_in, const int* in_sizes, int n_in,
                              void* d_out, int out_size)
{
    const float* pc   = (const float*)d_in[0];
    const float* feat = (const float*)d_in[1];
    const float* img1 = (const float*)d_in[2];
    const float* img2 = (const float*)d_in[3];
    const int*   qv1  = (const int*)d_in[5];
    const float* npc  = (const float*)d_in[6];
    const float* w1 = (const float*)d_in[7];
    const float* g1 = (const float*)d_in[8];
    const float* b1 = (const float*)d_in[9];
    const float* w2 = (const float*)d_in[10];
    const float* g2 = (const float*)d_in[11];
    const float* b2 = (const float*)d_in[12];
    const float* w3 = (const float*)d_in[13];
    const float* g3 = (const float*)d_in[14];
    const float* b3 = (const float*)d_in[15];
    const float* w4 = (const float*)d_in[16];
    const float* g4 = (const float*)d_in[17];
    const float* b4 = (const float*)d_in[18];
    float* out = (float*)d_out;

    __half *pX0, *pY1, *pY2, *pY3, *pY4;
    unsigned *pW1, *pW2, *pW3, *pW4;
    float *pSum, *pSq, *pSc, *pSh;
    cudaGetSymbolAddress((void**)&pX0, g_X0h);
    cudaGetSymbolAddress((void**)&pY1, g_Y1h);
    cudaGetSymbolAddress((void**)&pY2, g_Y2h);
    cudaGetSymbolAddress((void**)&pY3, g_Y3h);
    cudaGetSymbolAddress((void**)&pY4, g_Y4h);
    cudaGetSymbolAddress((void**)&pW1, g_Wp1);
    cudaGetSymbolAddress((void**)&pW2, g_Wp2);
    cudaGetSymbolAddress((void**)&pW3, g_Wp3);
    cudaGetSymbolAddress((void**)&pW4, g_Wp4);
    cudaGetSymbolAddress((void**)&pSum, g_sum);
    cudaGetSymbolAddress((void**)&pSq,  g_sq);
    cudaGetSymbolAddress((void**)&pSc,  g_sc);
    cudaGetSymbolAddress((void**)&pSh,  g_sh);

    k_idx<<<B_, 256>>>(pc, npc, qv1);
    k_prep<<<32, 256>>>(w1, w2, w3, w4);
    k_gather<<<B_ * PCTR, 256>>>(pc, feat, img1, img2, npc, out);

    const int GX = MTOT / 128;

    // L1: 64 <- 96(pad of 67), no norm-in
    k_gemm_h<64, 96, false, -1, 256><<<GX, 256>>>(pW1, pX0, pY1, nullptr, nullptr,
                                                  pSum + 0, pSq + 0, out);
    k_stats<<<1, 256>>>(0, g1, b1, 64);

    // L2: 128 <- 64, norm-in(L1), writes bn(Y1) to out ch [0,64)
    k_gemm_h<128, 64, true, 0, 256><<<GX, 256>>>(pW2, pY1, pY2, pSc + 0, pSh + 0,
                                                 pSum + 256, pSq + 256, out);
    k_stats<<<1, 256>>>(1, g2, b2, 128);

    // L3: 128 <- 128, norm-in(L2), writes bn(Y2) to out ch [128,256)
    k_gemm_h<128, 128, true, 128, 256><<<GX, 256>>>(pW3, pY2, pY3, pSc + 256, pSh + 256,
                                                    pSum + 512, pSq + 512, out);
    k_stats<<<1, 256>>>(2, g3, b3, 128);

    // L4: 256 <- 128, norm-in(L3), no out fusion
    k_gemm_h<256, 128, true, -1, 512><<<GX, 512>>>(pW4, pY3, pY4, pSc + 512, pSh + 512,
                                                   pSum + 768, pSq + 768, out);
    k_stats<<<1, 256>>>(3, g4, b4, 256);

    // bn(Y4) -> out ch [384,640)
    k_norm_out_h<<<2048, 256>>>(pY4, 3, 256, 384, out);
}